// round 2
// baseline (speedup 1.0000x reference)
#include <cuda_runtime.h>
#include <cuda_bf16.h>
#include <cstdint>

// Problem constants
#define B_SZ   8192
#define L_SZ   64
#define EMB    64
#define HID    128
#define G3     384     // 3*HID
#define OUTD   128

// ---------------- device scratch (no cudaMalloc allowed) ----------------
__device__ float g_xg[(size_t)B_SZ * L_SZ * G3];   // [t][b][gj], gj = g*128 + j  (~805 MB)
__device__ float g_Wih_t[EMB * G3];                // [k][gj]  transpose of W_ih
__device__ float g_Whh_t[HID * G3];                // [k][gj]  transpose of W_hh
__device__ float g_Wout_t[HID * OUTD];             // [k][o]   transpose of W_out
__device__ float g_cbias[G3];                      // b_ih + (b_hh for r,z only)

// ---------------- helpers ----------------
__device__ __forceinline__ float2 ffma2(float2 a, float2 b, float2 c) {
    unsigned long long au = *reinterpret_cast<unsigned long long*>(&a);
    unsigned long long bu = *reinterpret_cast<unsigned long long*>(&b);
    unsigned long long cu = *reinterpret_cast<unsigned long long*>(&c);
    unsigned long long du;
    asm("fma.rn.f32x2 %0, %1, %2, %3;" : "=l"(du) : "l"(au), "l"(bu), "l"(cu));
    return *reinterpret_cast<float2*>(&du);
}

__device__ __forceinline__ float fsig(float x) {
    // 1/(1+2^(-x*log2e)) via MUFU.EX2 + MUFU.RCP (~1e-7 rel err)
    float e;
    asm("ex2.approx.f32 %0, %1;" : "=f"(e) : "f"(-1.4426950408889634f * x));
    float r;
    asm("rcp.approx.f32 %0, %1;" : "=f"(r) : "f"(1.0f + e));
    return r;
}

__device__ __forceinline__ float ftanh(float x) {
    // tanh(x) = 2*sigmoid(2x) - 1
    float e;
    asm("ex2.approx.f32 %0, %1;" : "=f"(e) : "f"(-2.8853900817779268f * x));
    float r;
    asm("rcp.approx.f32 %0, %1;" : "=f"(r) : "f"(1.0f + e));
    return fmaf(2.0f, r, -1.0f);
}

// ---------------- prep: transposes + combined bias ----------------
__global__ void prep_kernel(const float* __restrict__ Wih,
                            const float* __restrict__ Whh,
                            const float* __restrict__ bih,
                            const float* __restrict__ bhh,
                            const float* __restrict__ Wout) {
    int i = blockIdx.x * blockDim.x + threadIdx.x;
    if (i < EMB * G3) {               // Wih_t[k][gj] = Wih[gj][k]
        int k = i / G3, gj = i % G3;
        g_Wih_t[i] = Wih[gj * EMB + k];
    }
    if (i < HID * G3) {               // Whh_t[k][gj] = Whh[gj][k]
        int k = i / G3, gj = i % G3;
        g_Whh_t[i] = Whh[gj * HID + k];
    }
    if (i < HID * OUTD) {             // Wout_t[k][o] = Wout[o][k]
        int k = i / OUTD, o = i % OUTD;
        g_Wout_t[i] = Wout[o * HID + k];
    }
    if (i < G3) {
        g_cbias[i] = bih[i] + (i < 2 * HID ? bhh[i] : 0.0f);
    }
}

// ---------------- phase 1: xg = embed[x] @ Wih^T + cbias ----------------
// grid (B/64, L), block 256, dyn smem = Wih_t(96KB) + e_s(64x66, 16.5KB)
#define P1_SMEM (EMB * G3 * 4 + 64 * 66 * 4)
__global__ __launch_bounds__(256, 2) void phase1_kernel(const int* __restrict__ x,
                                                        const float* __restrict__ embed) {
    extern __shared__ float sm1[];
    float* Ws = sm1;               // [k][gj] 64x384
    float* Es = sm1 + EMB * G3;    // [k][row] 64x66 (pad 2)
    const int tid = threadIdx.x;
    const int t = blockIdx.y;
    const int b0 = blockIdx.x * 64;

    // stage Wih_t
    {
        const float4* src = (const float4*)g_Wih_t;
        float4* dst = (float4*)Ws;
        #pragma unroll
        for (int i = tid; i < EMB * G3 / 4; i += 256) dst[i] = src[i];
    }
    // gather embedding rows, transposed into Es[k][row]
    {
        int row = tid >> 2, part = tid & 3;
        int idx = x[(size_t)(b0 + row) * L_SZ + t];
        const float4* er = (const float4*)(embed + (size_t)idx * EMB + part * 16);
        #pragma unroll
        for (int q = 0; q < 4; q++) {
            float4 v = er[q];
            int k = part * 16 + q * 4;
            Es[(k + 0) * 66 + row] = v.x;
            Es[(k + 1) * 66 + row] = v.y;
            Es[(k + 2) * 66 + row] = v.z;
            Es[(k + 3) * 66 + row] = v.w;
        }
    }
    __syncthreads();

    const int tx = tid & 31, ty = tid >> 5;
    float2 acc[3][2][8];
    #pragma unroll
    for (int g = 0; g < 3; g++)
        #pragma unroll
        for (int p = 0; p < 2; p++)
            #pragma unroll
            for (int b = 0; b < 8; b++) acc[g][p][b] = make_float2(0.f, 0.f);

    const float* wrow = Ws + tx * 4;
    const float* erow = Es + ty * 8;

    #pragma unroll 2
    for (int k = 0; k < EMB; k++) {
        float4 wr = *(const float4*)(wrow + k * G3);
        float4 wz = *(const float4*)(wrow + k * G3 + 128);
        float4 wn = *(const float4*)(wrow + k * G3 + 256);
        float2 w0[3] = {make_float2(wr.x, wr.y), make_float2(wz.x, wz.y), make_float2(wn.x, wn.y)};
        float2 w1[3] = {make_float2(wr.z, wr.w), make_float2(wz.z, wz.w), make_float2(wn.z, wn.w)};
        #pragma unroll
        for (int b = 0; b < 8; b++) {
            float e = erow[k * 66 + b];
            float2 e2 = make_float2(e, e);
            #pragma unroll
            for (int g = 0; g < 3; g++) {
                acc[g][0][b] = ffma2(w0[g], e2, acc[g][0][b]);
                acc[g][1][b] = ffma2(w1[g], e2, acc[g][1][b]);
            }
        }
    }

    float* obase = g_xg + ((size_t)t * B_SZ + b0) * G3;
    #pragma unroll
    for (int g = 0; g < 3; g++) {
        float4 cb = *(const float4*)(g_cbias + g * 128 + tx * 4);
        #pragma unroll
        for (int b = 0; b < 8; b++) {
            float4 o;
            o.x = acc[g][0][b].x + cb.x;
            o.y = acc[g][0][b].y + cb.y;
            o.z = acc[g][1][b].x + cb.z;
            o.w = acc[g][1][b].y + cb.w;
            *(float4*)(obase + (size_t)(ty * 8 + b) * G3 + g * 128 + tx * 4) = o;
        }
    }
}

// ---------------- phase 2: GRU recurrence + output projection ----------------
// grid 128, block 256, dyn smem = Whh_t(192KB) + h(128x65, 33.3KB)
#define HSTRIDE 65
#define P2_SMEM (HID * G3 * 4 + HID * HSTRIDE * 4)
__global__ __launch_bounds__(256, 1) void phase2_kernel(const float* __restrict__ bhh,
                                                        const float* __restrict__ bout,
                                                        float* __restrict__ out) {
    extern __shared__ float sm2[];
    float* Ws = sm2;                // [k][gj] 128x384
    float* Hs = sm2 + HID * G3;     // [k][b]  128x65

    const int tid = threadIdx.x;
    const int b0 = blockIdx.x * 64;

    {
        const float4* src = (const float4*)g_Whh_t;
        float4* dst = (float4*)Ws;
        #pragma unroll
        for (int i = tid; i < HID * G3 / 4; i += 256) dst[i] = src[i];
    }
    for (int i = tid; i < HID * HSTRIDE; i += 256) Hs[i] = 0.0f;

    const int tx = tid & 31, ty = tid >> 5;
    float4 pbn4 = *(const float4*)(bhh + 256 + tx * 4);
    float2 pbn0 = make_float2(pbn4.x, pbn4.y);
    float2 pbn1 = make_float2(pbn4.z, pbn4.w);
    __syncthreads();

    const float* wrow = Ws + tx * 4;
    const float* hrow = Hs + ty * 8;

    for (int t = 0; t < L_SZ; t++) {
        const float* xg = g_xg + ((size_t)t * B_SZ + b0 + ty * 8) * G3 + tx * 4;

        float2 ar[2][8], az[2][8], an[2][8];
        #pragma unroll
        for (int b = 0; b < 8; b++) {
            float4 vr = *(const float4*)(xg + (size_t)b * G3);
            float4 vz = *(const float4*)(xg + (size_t)b * G3 + 128);
            ar[0][b] = make_float2(vr.x, vr.y); ar[1][b] = make_float2(vr.z, vr.w);
            az[0][b] = make_float2(vz.x, vz.y); az[1][b] = make_float2(vz.z, vz.w);
            an[0][b] = pbn0;                    an[1][b] = pbn1;
        }

        #pragma unroll 2
        for (int k = 0; k < HID; k++) {
            float4 wr = *(const float4*)(wrow + k * G3);
            float4 wz = *(const float4*)(wrow + k * G3 + 128);
            float4 wn = *(const float4*)(wrow + k * G3 + 256);
            float2 wr0 = make_float2(wr.x, wr.y), wr1 = make_float2(wr.z, wr.w);
            float2 wz0 = make_float2(wz.x, wz.y), wz1 = make_float2(wz.z, wz.w);
            float2 wn0 = make_float2(wn.x, wn.y), wn1 = make_float2(wn.z, wn.w);
            #pragma unroll
            for (int b = 0; b < 8; b++) {
                float h = hrow[k * HSTRIDE + b];
                float2 h2 = make_float2(h, h);
                ar[0][b] = ffma2(wr0, h2, ar[0][b]);
                ar[1][b] = ffma2(wr1, h2, ar[1][b]);
                az[0][b] = ffma2(wz0, h2, az[0][b]);
                az[1][b] = ffma2(wz1, h2, az[1][b]);
                an[0][b] = ffma2(wn0, h2, an[0][b]);
                an[1][b] = ffma2(wn1, h2, an[1][b]);
            }
        }

        // gate math (reads old h; h writes happen after the barrier)
        float hnew[8][4];
        #pragma unroll
        for (int b = 0; b < 8; b++) {
            float4 xn4 = *(const float4*)(xg + (size_t)b * G3 + 256);
            float xn[4] = {xn4.x, xn4.y, xn4.z, xn4.w};
            float rr[4] = {ar[0][b].x, ar[0][b].y, ar[1][b].x, ar[1][b].y};
            float zz[4] = {az[0][b].x, az[0][b].y, az[1][b].x, az[1][b].y};
            float nn[4] = {an[0][b].x, an[0][b].y, an[1][b].x, an[1][b].y};
            #pragma unroll
            for (int j = 0; j < 4; j++) {
                float r = fsig(rr[j]);
                float z = fsig(zz[j]);
                float n = ftanh(fmaf(r, nn[j], xn[j]));
                float hold = Hs[(tx * 4 + j) * HSTRIDE + ty * 8 + b];
                hnew[b][j] = fmaf(z, hold - n, n);   // (1-z)*n + z*h
            }
        }
        __syncthreads();
        #pragma unroll
        for (int b = 0; b < 8; b++)
            #pragma unroll
            for (int j = 0; j < 4; j++)
                Hs[(tx * 4 + j) * HSTRIDE + ty * 8 + b] = hnew[b][j];
        __syncthreads();
    }

    // output projection: out[b][o] = sum_k Hs[k][b] * Wout_t[k][o] + bout[o]
    float2 oa[2][8];
    #pragma unroll
    for (int p = 0; p < 2; p++)
        #pragma unroll
        for (int b = 0; b < 8; b++) oa[p][b] = make_float2(0.f, 0.f);

    #pragma unroll 2
    for (int k = 0; k < HID; k++) {
        float4 w = __ldg((const float4*)(g_Wout_t + k * OUTD + tx * 4));
        float2 w0 = make_float2(w.x, w.y), w1 = make_float2(w.z, w.w);
        #pragma unroll
        for (int b = 0; b < 8; b++) {
            float h = hrow[k * HSTRIDE + b];
            float2 h2 = make_float2(h, h);
            oa[0][b] = ffma2(w0, h2, oa[0][b]);
            oa[1][b] = ffma2(w1, h2, oa[1][b]);
        }
    }
    float4 bo = *(const float4*)(bout + tx * 4);
    #pragma unroll
    for (int b = 0; b < 8; b++) {
        float4 o;
        o.x = oa[0][b].x + bo.x;
        o.y = oa[0][b].y + bo.y;
        o.z = oa[1][b].x + bo.z;
        o.w = oa[1][b].y + bo.w;
        *(float4*)(out + (size_t)(b0 + ty * 8 + b) * OUTD + tx * 4) = o;
    }
}

// ---------------- launch ----------------
extern "C" void kernel_launch(void* const* d_in, const int* in_sizes, int n_in,
                              void* d_out, int out_size) {
    const int*   x     = (const int*)d_in[0];
    const float* embed = (const float*)d_in[1];
    const float* Wih   = (const float*)d_in[2];
    const float* Whh   = (const float*)d_in[3];
    const float* bih   = (const float*)d_in[4];
    const float* bhh   = (const float*)d_in[5];
    const float* Wout  = (const float*)d_in[6];
    const float* bout  = (const float*)d_in[7];
    float* out = (float*)d_out;

    static bool attr_done = false;
    if (!attr_done) {
        cudaFuncSetAttribute(phase1_kernel, cudaFuncAttributeMaxDynamicSharedMemorySize, P1_SMEM);
        cudaFuncSetAttribute(phase2_kernel, cudaFuncAttributeMaxDynamicSharedMemorySize, P2_SMEM);
        attr_done = true;
    }

    prep_kernel<<<(HID * G3 + 255) / 256, 256>>>(Wih, Whh, bih, bhh, Wout);

    dim3 g1(B_SZ / 64, L_SZ);
    phase1_kernel<<<g1, 256, P1_SMEM>>>(x, embed);

    phase2_kernel<<<B_SZ / 64, 256, P2_SMEM>>>(bhh, bout, out);
}

// round 3
// speedup vs baseline: 1.4511x; 1.4511x over previous
#include <cuda_runtime.h>
#include <cuda_bf16.h>
#include <cstdint>

// Problem constants
#define B_SZ   8192
#define L_SZ   64
#define EMB    64
#define HID    128
#define G3     384     // 3*HID
#define OUTD   128
#define NVAL   1000

// ---------------- device scratch (no cudaMalloc allowed) ----------------
__device__ float g_tab[NVAL * G3];      // [v][gj] precomputed embed[v]@Wih^T + bias (1.5 MB, L2-hot)
__device__ float g_Wih_t[EMB * G3];     // [k][gj]
__device__ float g_Whh_t[HID * G3];     // [k][gj]
__device__ float g_Wout_t[HID * OUTD];  // [k][o]
__device__ float g_cbias[G3];           // b_ih + (b_hh for r,z only)

// ---------------- helpers ----------------
__device__ __forceinline__ float2 ffma2(float2 a, float2 b, float2 c) {
    unsigned long long au = *reinterpret_cast<unsigned long long*>(&a);
    unsigned long long bu = *reinterpret_cast<unsigned long long*>(&b);
    unsigned long long cu = *reinterpret_cast<unsigned long long*>(&c);
    unsigned long long du;
    asm("fma.rn.f32x2 %0, %1, %2, %3;" : "=l"(du) : "l"(au), "l"(bu), "l"(cu));
    return *reinterpret_cast<float2*>(&du);
}

__device__ __forceinline__ float fsig(float x) {
    float e;
    asm("ex2.approx.f32 %0, %1;" : "=f"(e) : "f"(-1.4426950408889634f * x));
    float r;
    asm("rcp.approx.f32 %0, %1;" : "=f"(r) : "f"(1.0f + e));
    return r;
}

__device__ __forceinline__ float ftanh(float x) {
    float e;
    asm("ex2.approx.f32 %0, %1;" : "=f"(e) : "f"(-2.8853900817779268f * x));
    float r;
    asm("rcp.approx.f32 %0, %1;" : "=f"(r) : "f"(1.0f + e));
    return fmaf(2.0f, r, -1.0f);
}

// ---------------- prep: transposes + combined bias ----------------
__global__ void prep_kernel(const float* __restrict__ Wih,
                            const float* __restrict__ Whh,
                            const float* __restrict__ bih,
                            const float* __restrict__ bhh,
                            const float* __restrict__ Wout) {
    int i = blockIdx.x * blockDim.x + threadIdx.x;
    if (i < EMB * G3) {
        int k = i / G3, gj = i % G3;
        g_Wih_t[i] = Wih[gj * EMB + k];
    }
    if (i < HID * G3) {
        int k = i / G3, gj = i % G3;
        g_Whh_t[i] = Whh[gj * HID + k];
    }
    if (i < HID * OUTD) {
        int k = i / OUTD, o = i % OUTD;
        g_Wout_t[i] = Wout[o * HID + k];
    }
    if (i < G3) {
        g_cbias[i] = bih[i] + (i < 2 * HID ? bhh[i] : 0.0f);
    }
}

// ---------------- table: tab[v][gj] = sum_k embed[v][k] * Wih_t[k][gj] + cbias[gj] ----------------
__global__ void table_kernel(const float* __restrict__ embed) {
    __shared__ float es[EMB];
    const int v = blockIdx.x;
    const int gj = threadIdx.x;
    if (gj < EMB) es[gj] = embed[v * EMB + gj];
    __syncthreads();
    float acc = 0.0f;
    #pragma unroll 8
    for (int k = 0; k < EMB; k++)
        acc = fmaf(es[k], g_Wih_t[k * G3 + gj], acc);
    g_tab[v * G3 + gj] = acc + g_cbias[gj];
}

// ---------------- phase 2: GRU recurrence + output projection ----------------
// grid 128, block 256, dyn smem = Whh_t(192KB) + h(128x65, 33.3KB)
#define HSTRIDE 65
#define P2_SMEM (HID * G3 * 4 + HID * HSTRIDE * 4)
__global__ __launch_bounds__(256, 1) void phase2_kernel(const int* __restrict__ x,
                                                        const float* __restrict__ bhh,
                                                        const float* __restrict__ bout,
                                                        float* __restrict__ out) {
    extern __shared__ float sm2[];
    float* Ws = sm2;                // [k][gj] 128x384
    float* Hs = sm2 + HID * G3;     // [k][b]  128x65

    const int tid = threadIdx.x;
    const int b0 = blockIdx.x * 64;
    const float* __restrict__ tab = g_tab;

    {
        const float4* src = (const float4*)g_Whh_t;
        float4* dst = (float4*)Ws;
        #pragma unroll
        for (int i = tid; i < HID * G3 / 4; i += 256) dst[i] = src[i];
    }
    for (int i = tid; i < HID * HSTRIDE; i += 256) Hs[i] = 0.0f;

    const int tx = tid & 31, ty = tid >> 5;
    float4 pbn4 = *(const float4*)(bhh + 256 + tx * 4);
    float2 pbn0 = make_float2(pbn4.x, pbn4.y);
    float2 pbn1 = make_float2(pbn4.z, pbn4.w);
    __syncthreads();

    const float* wrow = Ws + tx * 4;
    const float* hrow = Hs + ty * 8;

    for (int t = 0; t < L_SZ; t++) {
        // gather token table rows: idx per batch row, xg slices from L2-resident table
        int idx[8];
        #pragma unroll
        for (int b = 0; b < 8; b++)
            idx[b] = x[(size_t)(b0 + ty * 8 + b) * L_SZ + t];

        float2 ar[2][8], az[2][8], an[2][8];
        #pragma unroll
        for (int b = 0; b < 8; b++) {
            const float* trow = tab + (size_t)idx[b] * G3 + tx * 4;
            float4 vr = __ldg((const float4*)(trow));
            float4 vz = __ldg((const float4*)(trow + 128));
            ar[0][b] = make_float2(vr.x, vr.y); ar[1][b] = make_float2(vr.z, vr.w);
            az[0][b] = make_float2(vz.x, vz.y); az[1][b] = make_float2(vz.z, vz.w);
            an[0][b] = pbn0;                    an[1][b] = pbn1;
        }

        #pragma unroll 2
        for (int k = 0; k < HID; k++) {
            float4 wr = *(const float4*)(wrow + k * G3);
            float4 wz = *(const float4*)(wrow + k * G3 + 128);
            float4 wn = *(const float4*)(wrow + k * G3 + 256);
            float2 wr0 = make_float2(wr.x, wr.y), wr1 = make_float2(wr.z, wr.w);
            float2 wz0 = make_float2(wz.x, wz.y), wz1 = make_float2(wz.z, wz.w);
            float2 wn0 = make_float2(wn.x, wn.y), wn1 = make_float2(wn.z, wn.w);
            #pragma unroll
            for (int b = 0; b < 8; b++) {
                float h = hrow[k * HSTRIDE + b];
                float2 h2 = make_float2(h, h);
                ar[0][b] = ffma2(wr0, h2, ar[0][b]);
                ar[1][b] = ffma2(wr1, h2, ar[1][b]);
                az[0][b] = ffma2(wz0, h2, az[0][b]);
                az[1][b] = ffma2(wz1, h2, az[1][b]);
                an[0][b] = ffma2(wn0, h2, an[0][b]);
                an[1][b] = ffma2(wn1, h2, an[1][b]);
            }
        }

        // gate math (reads old h; h writes happen after the barrier)
        float hnew[8][4];
        #pragma unroll
        for (int b = 0; b < 8; b++) {
            float4 xn4 = __ldg((const float4*)(tab + (size_t)idx[b] * G3 + 256 + tx * 4));
            float xn[4] = {xn4.x, xn4.y, xn4.z, xn4.w};
            float rr[4] = {ar[0][b].x, ar[0][b].y, ar[1][b].x, ar[1][b].y};
            float zz[4] = {az[0][b].x, az[0][b].y, az[1][b].x, az[1][b].y};
            float nn[4] = {an[0][b].x, an[0][b].y, an[1][b].x, an[1][b].y};
            #pragma unroll
            for (int j = 0; j < 4; j++) {
                float r = fsig(rr[j]);
                float z = fsig(zz[j]);
                float n = ftanh(fmaf(r, nn[j], xn[j]));
                float hold = Hs[(tx * 4 + j) * HSTRIDE + ty * 8 + b];
                hnew[b][j] = fmaf(z, hold - n, n);   // (1-z)*n + z*h
            }
        }
        __syncthreads();
        #pragma unroll
        for (int b = 0; b < 8; b++)
            #pragma unroll
            for (int j = 0; j < 4; j++)
                Hs[(tx * 4 + j) * HSTRIDE + ty * 8 + b] = hnew[b][j];
        __syncthreads();
    }

    // output projection: out[b][o] = sum_k Hs[k][b] * Wout_t[k][o] + bout[o]
    float2 oa[2][8];
    #pragma unroll
    for (int p = 0; p < 2; p++)
        #pragma unroll
        for (int b = 0; b < 8; b++) oa[p][b] = make_float2(0.f, 0.f);

    #pragma unroll 2
    for (int k = 0; k < HID; k++) {
        float4 w = __ldg((const float4*)(g_Wout_t + k * OUTD + tx * 4));
        float2 w0 = make_float2(w.x, w.y), w1 = make_float2(w.z, w.w);
        #pragma unroll
        for (int b = 0; b < 8; b++) {
            float h = hrow[k * HSTRIDE + b];
            float2 h2 = make_float2(h, h);
            oa[0][b] = ffma2(w0, h2, oa[0][b]);
            oa[1][b] = ffma2(w1, h2, oa[1][b]);
        }
    }
    float4 bo = *(const float4*)(bout + tx * 4);
    #pragma unroll
    for (int b = 0; b < 8; b++) {
        float4 o;
        o.x = oa[0][b].x + bo.x;
        o.y = oa[0][b].y + bo.y;
        o.z = oa[1][b].x + bo.z;
        o.w = oa[1][b].y + bo.w;
        *(float4*)(out + (size_t)(b0 + ty * 8 + b) * OUTD + tx * 4) = o;
    }
}

// ---------------- launch ----------------
extern "C" void kernel_launch(void* const* d_in, const int* in_sizes, int n_in,
                              void* d_out, int out_size) {
    const int*   x     = (const int*)d_in[0];
    const float* embed = (const float*)d_in[1];
    const float* Wih   = (const float*)d_in[2];
    const float* Whh   = (const float*)d_in[3];
    const float* bih   = (const float*)d_in[4];
    const float* bhh   = (const float*)d_in[5];
    const float* Wout  = (const float*)d_in[6];
    const float* bout  = (const float*)d_in[7];
    float* out = (float*)d_out;

    static bool attr_done = false;
    if (!attr_done) {
        cudaFuncSetAttribute(phase2_kernel, cudaFuncAttributeMaxDynamicSharedMemorySize, P2_SMEM);
        attr_done = true;
    }

    prep_kernel<<<(HID * G3 + 255) / 256, 256>>>(Wih, Whh, bih, bhh, Wout);
    table_kernel<<<NVAL, G3>>>(embed);
    phase2_kernel<<<B_SZ / 64, 256, P2_SMEM>>>(x, bhh, bout, out);
}